// round 1
// baseline (speedup 1.0000x reference)
#include <cuda_runtime.h>
#include <cuda_bf16.h>
#include <math.h>

// Problem constants
#define B_    64
#define CIN_  256
#define HID_  256
#define COUT_ 10
#define EPS_  1e-5f

// Intermediate buffers (device globals; no allocation allowed)
__device__ float g_kfeat[B_ * HID_ * 5 * 5];        // relu(bn(conv3x3(kernel)))   (64,256,5,5)
__device__ float g_sfeat[B_ * HID_ * 29 * 29];      // relu(bn(conv3x3(search)))   (64,256,29,29)
__device__ float g_feat [B_ * HID_ * 3 * 25 * 25];  // multixcorr concat           (64,768,25,25)
__device__ float g_f2   [B_ * HID_ * 25 * 25];      // bn(conv1x1 wd)              (64,256,25,25)
__device__ float g_h    [B_ * HID_ * 25 * 25];      // relu(bn(conv1x1 wh1))       (64,256,25,25)

// ---------------------------------------------------------------------------
// 3x3 VALID conv + BN + ReLU.  grid = (H_OUT, B), block = 256 (thread = oc).
// Each block computes one output row (all W_OUT cols) for all 256 oc of one b.
// ---------------------------------------------------------------------------
template <int H_IN, int W_IN>
__global__ void conv3x3_bn_relu_kernel(const float* __restrict__ in,
                                       const float* __restrict__ w,
                                       const float* __restrict__ bn,
                                       float* __restrict__ out) {
    constexpr int H_OUT = H_IN - 2;
    constexpr int W_OUT = W_IN - 2;
    const int y  = blockIdx.x;
    const int b  = blockIdx.y;
    const int oc = threadIdx.x;   // 0..255

    __shared__ float srow[3][W_IN];

    float acc[W_OUT];
#pragma unroll
    for (int x = 0; x < W_OUT; x++) acc[x] = 0.f;

    const float* inb = in + (size_t)b * CIN_ * H_IN * W_IN;

    for (int ic = 0; ic < CIN_; ic++) {
        __syncthreads();
        const float* ip = inb + (size_t)ic * H_IN * W_IN + y * W_IN;
        for (int i = threadIdx.x; i < 3 * W_IN; i += blockDim.x) {
            int r = i / W_IN, cx = i - r * W_IN;
            srow[r][cx] = ip[r * W_IN + cx];
        }
        __syncthreads();

        const float* wp = w + ((size_t)oc * CIN_ + ic) * 9;
        const float w0 = wp[0], w1 = wp[1], w2 = wp[2];
        const float w3 = wp[3], w4 = wp[4], w5 = wp[5];
        const float w6 = wp[6], w7 = wp[7], w8 = wp[8];

#pragma unroll
        for (int x = 0; x < W_OUT; x++) {
            float a = acc[x];
            a = fmaf(srow[0][x    ], w0, a);
            a = fmaf(srow[0][x + 1], w1, a);
            a = fmaf(srow[0][x + 2], w2, a);
            a = fmaf(srow[1][x    ], w3, a);
            a = fmaf(srow[1][x + 1], w4, a);
            a = fmaf(srow[1][x + 2], w5, a);
            a = fmaf(srow[2][x    ], w6, a);
            a = fmaf(srow[2][x + 1], w7, a);
            a = fmaf(srow[2][x + 2], w8, a);
            acc[x] = a;
        }
    }

    // BN fold + ReLU.  bn layout: (4, HID) = gamma, beta, mean, var
    const float g  = bn[oc];
    const float be = bn[HID_ + oc];
    const float m  = bn[2 * HID_ + oc];
    const float v  = bn[3 * HID_ + oc];
    const float inv  = g / sqrtf(v + EPS_);
    const float bias = be - m * inv;

    float* ob = out + (((size_t)b * HID_ + oc) * H_OUT + y) * W_OUT;
#pragma unroll
    for (int x = 0; x < W_OUT; x++) {
        float val = acc[x] * inv + bias;
        ob[x] = fmaxf(val, 0.f);
    }
}

// ---------------------------------------------------------------------------
// Multi-scale depthwise xcorr.  The three crops are nested windows:
//   feat[b, i*256+c, y, x] = sum_{dy,dx in [i, 4-i]} s[b,c,y+dy,x+dx] * k[b,c,dy,dx]
// One pass over the 5x5 window yields all three sums.
// grid = (256, 64) -> (c, b), block = 256 threads over 625 output pixels.
// ---------------------------------------------------------------------------
__global__ void multixcorr_kernel(const float* __restrict__ s,
                                  const float* __restrict__ k,
                                  float* __restrict__ feat) {
    const int c = blockIdx.x;
    const int b = blockIdx.y;

    __shared__ float ss[29 * 29];
    __shared__ float kk[25];

    const float* sp = s + ((size_t)b * HID_ + c) * 29 * 29;
    const float* kp = k + ((size_t)b * HID_ + c) * 25;

    for (int i = threadIdx.x; i < 29 * 29; i += blockDim.x) ss[i] = sp[i];
    if (threadIdx.x < 25) kk[threadIdx.x] = kp[threadIdx.x];
    __syncthreads();

    float* f0 = feat + ((size_t)b * (3 * HID_) + c)            * 625;
    float* f1 = feat + ((size_t)b * (3 * HID_) + HID_ + c)     * 625;
    float* f2 = feat + ((size_t)b * (3 * HID_) + 2 * HID_ + c) * 625;

    for (int p = threadIdx.x; p < 625; p += blockDim.x) {
        const int y = p / 25, x = p - (p / 25) * 25;
        float s_full = 0.f, s_in = 0.f;
#pragma unroll
        for (int dy = 0; dy < 5; dy++) {
#pragma unroll
            for (int dx = 0; dx < 5; dx++) {
                float vv = ss[(y + dy) * 29 + (x + dx)] * kk[dy * 5 + dx];
                s_full += vv;
                if (dy >= 1 && dy <= 3 && dx >= 1 && dx <= 3) s_in += vv;
            }
        }
        f0[p] = s_full;
        f1[p] = s_in;
        f2[p] = ss[(y + 2) * 29 + (x + 2)] * kk[12];
    }
}

// ---------------------------------------------------------------------------
// 1x1 conv + BN (+ optional ReLU) over (B, CIN, 25, 25) -> (B, 256, 25, 25).
// grid = (25 rows, B), block = 256 (thread = oc). Pixel-row tile in smem.
// ---------------------------------------------------------------------------
template <int KIN, bool RELU>
__global__ void conv1x1_bn_kernel(const float* __restrict__ in,
                                  const float* __restrict__ w,
                                  const float* __restrict__ bn,
                                  float* __restrict__ out) {
    const int row = blockIdx.x;   // 0..24
    const int b   = blockIdx.y;
    const int oc  = threadIdx.x;  // 0..255

    __shared__ float tile[32][25];

    float acc[25];
#pragma unroll
    for (int x = 0; x < 25; x++) acc[x] = 0.f;

    const float* ib = in + (size_t)b * KIN * 625 + row * 25;

    for (int ic0 = 0; ic0 < KIN; ic0 += 32) {
        __syncthreads();
        for (int i = threadIdx.x; i < 32 * 25; i += blockDim.x) {
            int ic = i / 25, x = i - ic * 25;
            tile[ic][x] = ib[(size_t)(ic0 + ic) * 625 + x];
        }
        __syncthreads();

        const float4* wp = reinterpret_cast<const float4*>(w + (size_t)oc * KIN + ic0);
#pragma unroll
        for (int i4 = 0; i4 < 8; i4++) {
            float4 wv = wp[i4];
#pragma unroll
            for (int x = 0; x < 25; x++) acc[x] = fmaf(tile[i4 * 4 + 0][x], wv.x, acc[x]);
#pragma unroll
            for (int x = 0; x < 25; x++) acc[x] = fmaf(tile[i4 * 4 + 1][x], wv.y, acc[x]);
#pragma unroll
            for (int x = 0; x < 25; x++) acc[x] = fmaf(tile[i4 * 4 + 2][x], wv.z, acc[x]);
#pragma unroll
            for (int x = 0; x < 25; x++) acc[x] = fmaf(tile[i4 * 4 + 3][x], wv.w, acc[x]);
        }
    }

    const float g  = bn[oc];
    const float be = bn[HID_ + oc];
    const float m  = bn[2 * HID_ + oc];
    const float v  = bn[3 * HID_ + oc];
    const float inv  = g / sqrtf(v + EPS_);
    const float bias = be - m * inv;

    float* ob = out + (((size_t)b * HID_ + oc) * 25 + row) * 25;
#pragma unroll
    for (int x = 0; x < 25; x++) {
        float val = acc[x] * inv + bias;
        ob[x] = RELU ? fmaxf(val, 0.f) : val;
    }
}

// ---------------------------------------------------------------------------
// Final 1x1 conv: (B,256,625) x (10,256) + bias -> (B,10,625)
// grid = B, block = 256 (thread = pixel, strided).
// ---------------------------------------------------------------------------
__global__ void conv1x1_out_kernel(const float* __restrict__ in,
                                   const float* __restrict__ w,
                                   const float* __restrict__ bias,
                                   float* __restrict__ out) {
    const int b = blockIdx.x;

    __shared__ float wsm[COUT_ * HID_];
    for (int i = threadIdx.x; i < COUT_ * HID_; i += blockDim.x) wsm[i] = w[i];
    __syncthreads();

    const float* ib = in + (size_t)b * HID_ * 625;
    float* ob = out + (size_t)b * COUT_ * 625;

    for (int p = threadIdx.x; p < 625; p += blockDim.x) {
        float acc[COUT_];
#pragma unroll
        for (int o = 0; o < COUT_; o++) acc[o] = bias[o];
        for (int c = 0; c < HID_; c++) {
            float vv = ib[(size_t)c * 625 + p];
#pragma unroll
            for (int o = 0; o < COUT_; o++) acc[o] = fmaf(vv, wsm[o * HID_ + c], acc[o]);
        }
#pragma unroll
        for (int o = 0; o < COUT_; o++) ob[(size_t)o * 625 + p] = acc[o];
    }
}

// ---------------------------------------------------------------------------
// Launch. Input order: kernel, search, wk, bnk, ws, bns, wd, bnd, wh1, bnh, wh2, bh2
// ---------------------------------------------------------------------------
extern "C" void kernel_launch(void* const* d_in, const int* in_sizes, int n_in,
                              void* d_out, int out_size) {
    const float* kernel_in = (const float*)d_in[0];
    const float* search_in = (const float*)d_in[1];
    const float* wk  = (const float*)d_in[2];
    const float* bnk = (const float*)d_in[3];
    const float* ws  = (const float*)d_in[4];
    const float* bns = (const float*)d_in[5];
    const float* wd  = (const float*)d_in[6];
    const float* bnd = (const float*)d_in[7];
    const float* wh1 = (const float*)d_in[8];
    const float* bnh = (const float*)d_in[9];
    const float* wh2 = (const float*)d_in[10];
    const float* bh2 = (const float*)d_in[11];
    float* out = (float*)d_out;

    float *kfeat, *sfeat, *feat, *f2, *h;
    cudaGetSymbolAddress((void**)&kfeat, g_kfeat);
    cudaGetSymbolAddress((void**)&sfeat, g_sfeat);
    cudaGetSymbolAddress((void**)&feat,  g_feat);
    cudaGetSymbolAddress((void**)&f2,    g_f2);
    cudaGetSymbolAddress((void**)&h,     g_h);

    // 1) kernel branch: (64,256,7,7) -> (64,256,5,5)
    conv3x3_bn_relu_kernel<7, 7><<<dim3(5, B_), 256>>>(kernel_in, wk, bnk, kfeat);
    // 2) search branch: (64,256,31,31) -> (64,256,29,29)
    conv3x3_bn_relu_kernel<31, 31><<<dim3(29, B_), 256>>>(search_in, ws, bns, sfeat);
    // 3) multi-scale depthwise xcorr -> (64,768,25,25)
    multixcorr_kernel<<<dim3(HID_, B_), 256>>>(sfeat, kfeat, feat);
    // 4) 1x1 conv wd + bn (no relu): 768 -> 256
    conv1x1_bn_kernel<3 * HID_, false><<<dim3(25, B_), 256>>>(feat, wd, bnd, f2);
    // 5) 1x1 conv wh1 + bn + relu: 256 -> 256
    conv1x1_bn_kernel<HID_, true><<<dim3(25, B_), 256>>>(f2, wh1, bnh, h);
    // 6) 1x1 conv wh2 + bias: 256 -> 10
    conv1x1_out_kernel<<<dim3(B_), 256>>>(h, wh2, bh2, out);
}

// round 2
// speedup vs baseline: 3.1951x; 3.1951x over previous
#include <cuda_runtime.h>
#include <math.h>

#define B_    64
#define CIN_  256
#define HID_  256
#define COUT_ 10
#define EPS_  1e-5f

// Intermediates
__device__ float g_kfeat[B_ * HID_ * 25];        // (64,256,5,5)
__device__ float g_sfeat[B_ * HID_ * 841];       // (64,256,29,29)
__device__ float g_feat [B_ * HID_ * 3 * 625];   // (64,768,25,25)
__device__ float g_f2   [B_ * HID_ * 625];       // (64,256,25,25)
__device__ float g_h    [B_ * HID_ * 625];       // (64,256,25,25)
// Transposed weights: [k][oc], oc contiguous
__device__ float g_wt3k[2304 * 256];
__device__ float g_wt3s[2304 * 256];
__device__ float g_wtd [768 * 256];
__device__ float g_wth1[256 * 256];

// ---------------------------------------------------------------------------
// Weight transposes (run every launch; tiny)
// w[oc][ic][3][3] -> wt[(tap*256+ic)][oc]   (tap = ky*3+kx)
// ---------------------------------------------------------------------------
__global__ void transpose_w3_kernel(const float* __restrict__ w,
                                    float* __restrict__ wt) {
    int idx = blockIdx.x * 256 + threadIdx.x;
    if (idx >= 2304 * 256) return;
    int oc  = idx & 255;
    int t   = idx >> 8;          // tap*256 + ic
    int tap = t >> 8;
    int ic  = t & 255;
    wt[idx] = w[(size_t)oc * 2304 + ic * 9 + tap];
}

// w[oc][k] -> wt[k][oc]
template <int K>
__global__ void transpose_w1_kernel(const float* __restrict__ w,
                                    float* __restrict__ wt) {
    int idx = blockIdx.x * 256 + threadIdx.x;
    if (idx >= K * 256) return;
    int oc = idx & 255;
    int k  = idx >> 8;
    wt[idx] = w[(size_t)oc * K + k];
}

// ---------------------------------------------------------------------------
// Implicit-GEMM 3x3 VALID conv + BN + ReLU.
// C[oc][p] , p in [0, B*HOUT*WOUT), K = 2304 (tap-major: k = tap*256 + ic).
// Tile 64(oc) x 64(px) x 16(k), 128 threads, 8x4 micro-tile.
// ---------------------------------------------------------------------------
template <int H_IN, int W_IN>
__global__ void gemm_conv3x3_kernel(const float* __restrict__ in,
                                    const float* __restrict__ wt,
                                    const float* __restrict__ bn,
                                    float* __restrict__ out) {
    constexpr int HOUT = H_IN - 2;
    constexpr int WOUT = W_IN - 2;
    constexpr int PXB  = HOUT * WOUT;
    constexpr int KT   = 2304;

    const int tid = threadIdx.x;
    const int tm  = tid >> 4;        // 0..7
    const int tn  = tid & 15;        // 0..15
    const int oc0 = blockIdx.y * 64;
    const int p0  = blockIdx.x * 64;

    __shared__ float4 As4[16][16];   // [k][m/4]
    __shared__ float4 Bs4[16][16];   // [k][n/4]
    float* Bs = (float*)Bs4;

    // B-gather: this thread's pixel column is fixed across all K stages
    const int n_b  = tid & 63;
    const int krow = tid >> 6;       // 0 or 1
    {
    }
    const int p   = p0 + n_b;
    const int b   = p / PXB;
    const int rem = p - b * PXB;
    const int y   = rem / WOUT;
    const int x   = rem - y * WOUT;
    const float* inbase = in + ((size_t)(b * CIN_) * H_IN + y) * W_IN + x;

    float acc[8][4];
#pragma unroll
    for (int i = 0; i < 8; i++)
#pragma unroll
        for (int j = 0; j < 4; j++) acc[i][j] = 0.f;

    for (int k0 = 0; k0 < KT; k0 += 16) {
        __syncthreads();
        // A tile: coalesced float4 from transposed weights
#pragma unroll
        for (int i = 0; i < 2; i++) {
            int f  = i * 128 + tid;
            int k  = f >> 4;
            int m4 = f & 15;
            As4[k][m4] = *(const float4*)(wt + (size_t)(k0 + k) * 256 + oc0 + m4 * 4);
        }
        // B tile: im2col gather (k -> tap, ic)
#pragma unroll
        for (int i = 0; i < 8; i++) {
            int kl  = i * 2 + krow;
            int k   = k0 + kl;
            int tap = k >> 8;
            int ic  = k & 255;
            int ky  = tap / 3;
            int kx  = tap - ky * 3;
            Bs[kl * 64 + n_b] = inbase[ic * (H_IN * W_IN) + ky * W_IN + kx];
        }
        __syncthreads();

#pragma unroll
        for (int k = 0; k < 16; k++) {
            float4 a0 = As4[k][tm * 2];
            float4 a1 = As4[k][tm * 2 + 1];
            float4 bv = Bs4[k][tn];
            float am[8] = {a0.x, a0.y, a0.z, a0.w, a1.x, a1.y, a1.z, a1.w};
            float bb[4] = {bv.x, bv.y, bv.z, bv.w};
#pragma unroll
            for (int i = 0; i < 8; i++)
#pragma unroll
                for (int j = 0; j < 4; j++)
                    acc[i][j] = fmaf(am[i], bb[j], acc[i][j]);
        }
    }

    // Epilogue: BN fold + ReLU, scatter to NCHW
#pragma unroll
    for (int i = 0; i < 8; i++) {
        const int oc = oc0 + tm * 8 + i;
        const float g  = bn[oc];
        const float be = bn[256 + oc];
        const float mm = bn[512 + oc];
        const float vv = bn[768 + oc];
        const float inv  = g / sqrtf(vv + EPS_);
        const float bias = be - mm * inv;
#pragma unroll
        for (int j = 0; j < 4; j++) {
            const int pq = p0 + tn * 4 + j;
            const int bq = pq / PXB;
            const int rq = pq - bq * PXB;
            float val = acc[i][j] * inv + bias;
            out[(size_t)(bq * 256 + oc) * PXB + rq] = fmaxf(val, 0.f);
        }
    }
}

// ---------------------------------------------------------------------------
// 1x1 conv as GEMM + BN (+ReLU).  C[oc][p], p in [0, B*625), K = KT.
// Same 64x64x16 tiling.
// ---------------------------------------------------------------------------
template <int KT, bool RELU>
__global__ void gemm_1x1_kernel(const float* __restrict__ in,
                                const float* __restrict__ wt,
                                const float* __restrict__ bn,
                                float* __restrict__ out) {
    const int tid = threadIdx.x;
    const int tm  = tid >> 4;
    const int tn  = tid & 15;
    const int oc0 = blockIdx.y * 64;
    const int p0  = blockIdx.x * 64;

    __shared__ float4 As4[16][16];
    __shared__ float4 Bs4[16][16];
    float* Bs = (float*)Bs4;

    const int n_b  = tid & 63;
    const int krow = tid >> 6;
    const int p  = p0 + n_b;
    const int b  = p / 625;
    const int pp = p - b * 625;
    const float* inbase = in + (size_t)b * KT * 625 + pp;

    float acc[8][4];
#pragma unroll
    for (int i = 0; i < 8; i++)
#pragma unroll
        for (int j = 0; j < 4; j++) acc[i][j] = 0.f;

    for (int k0 = 0; k0 < KT; k0 += 16) {
        __syncthreads();
#pragma unroll
        for (int i = 0; i < 2; i++) {
            int f  = i * 128 + tid;
            int k  = f >> 4;
            int m4 = f & 15;
            As4[k][m4] = *(const float4*)(wt + (size_t)(k0 + k) * 256 + oc0 + m4 * 4);
        }
#pragma unroll
        for (int i = 0; i < 8; i++) {
            int kl = i * 2 + krow;
            Bs[kl * 64 + n_b] = inbase[(size_t)(k0 + kl) * 625];
        }
        __syncthreads();

#pragma unroll
        for (int k = 0; k < 16; k++) {
            float4 a0 = As4[k][tm * 2];
            float4 a1 = As4[k][tm * 2 + 1];
            float4 bv = Bs4[k][tn];
            float am[8] = {a0.x, a0.y, a0.z, a0.w, a1.x, a1.y, a1.z, a1.w};
            float bb[4] = {bv.x, bv.y, bv.z, bv.w};
#pragma unroll
            for (int i = 0; i < 8; i++)
#pragma unroll
                for (int j = 0; j < 4; j++)
                    acc[i][j] = fmaf(am[i], bb[j], acc[i][j]);
        }
    }

#pragma unroll
    for (int i = 0; i < 8; i++) {
        const int oc = oc0 + tm * 8 + i;
        const float g  = bn[oc];
        const float be = bn[256 + oc];
        const float mm = bn[512 + oc];
        const float vv = bn[768 + oc];
        const float inv  = g / sqrtf(vv + EPS_);
        const float bias = be - mm * inv;
#pragma unroll
        for (int j = 0; j < 4; j++) {
            const int pq = p0 + tn * 4 + j;
            const int bq = pq / 625;
            const int rq = pq - bq * 625;
            float val = acc[i][j] * inv + bias;
            if (RELU) val = fmaxf(val, 0.f);
            out[(size_t)(bq * 256 + oc) * 625 + rq] = val;
        }
    }
}

// ---------------------------------------------------------------------------
// Multi-scale depthwise xcorr (all 3 nested scales in one 5x5 pass).
// grid = (256, 64) -> (c, b), 256 threads over 625 pixels.
// ---------------------------------------------------------------------------
__global__ void multixcorr_kernel(const float* __restrict__ s,
                                  const float* __restrict__ k,
                                  float* __restrict__ feat) {
    const int c = blockIdx.x;
    const int b = blockIdx.y;

    __shared__ float ss[29 * 29];
    __shared__ float kk[25];

    const float* sp = s + ((size_t)b * HID_ + c) * 841;
    const float* kp = k + ((size_t)b * HID_ + c) * 25;

    for (int i = threadIdx.x; i < 841; i += blockDim.x) ss[i] = sp[i];
    if (threadIdx.x < 25) kk[threadIdx.x] = kp[threadIdx.x];
    __syncthreads();

    float* f0 = feat + ((size_t)b * (3 * HID_) + c) * 625;
    float* f1 = f0 + (size_t)HID_ * 625;
    float* f2 = f1 + (size_t)HID_ * 625;

    for (int p = threadIdx.x; p < 625; p += blockDim.x) {
        const int y = p / 25, x = p - (p / 25) * 25;
        float s_full = 0.f, s_in = 0.f;
#pragma unroll
        for (int dy = 0; dy < 5; dy++)
#pragma unroll
            for (int dx = 0; dx < 5; dx++) {
                float vv = ss[(y + dy) * 29 + (x + dx)] * kk[dy * 5 + dx];
                s_full += vv;
                if (dy >= 1 && dy <= 3 && dx >= 1 && dx <= 3) s_in += vv;
            }
        f0[p] = s_full;
        f1[p] = s_in;
        f2[p] = ss[(y + 2) * 29 + (x + 2)] * kk[12];
    }
}

// ---------------------------------------------------------------------------
// Final 1x1: (B,256,625) x (10,256) + bias -> (B,10,625). grid (B, 5).
// ---------------------------------------------------------------------------
__global__ void conv1x1_out_kernel(const float* __restrict__ in,
                                   const float* __restrict__ w,
                                   const float* __restrict__ bias,
                                   float* __restrict__ out) {
    const int b = blockIdx.x;
    const int chunk = blockIdx.y;

    __shared__ float wsm[COUT_ * HID_];
    for (int i = threadIdx.x; i < COUT_ * HID_; i += blockDim.x) wsm[i] = w[i];
    __syncthreads();

    const float* ib = in + (size_t)b * HID_ * 625;
    float* ob = out + (size_t)b * COUT_ * 625;

    const int pend = min(625, (chunk + 1) * 125);
    for (int p = chunk * 125 + threadIdx.x; p < pend; p += blockDim.x) {
        float acc[COUT_];
#pragma unroll
        for (int o = 0; o < COUT_; o++) acc[o] = bias[o];
        for (int c = 0; c < HID_; c++) {
            float vv = ib[(size_t)c * 625 + p];
#pragma unroll
            for (int o = 0; o < COUT_; o++) acc[o] = fmaf(vv, wsm[o * HID_ + c], acc[o]);
        }
#pragma unroll
        for (int o = 0; o < COUT_; o++) ob[(size_t)o * 625 + p] = acc[o];
    }
}

// ---------------------------------------------------------------------------
extern "C" void kernel_launch(void* const* d_in, const int* in_sizes, int n_in,
                              void* d_out, int out_size) {
    const float* kernel_in = (const float*)d_in[0];
    const float* search_in = (const float*)d_in[1];
    const float* wk  = (const float*)d_in[2];
    const float* bnk = (const float*)d_in[3];
    const float* ws  = (const float*)d_in[4];
    const float* bns = (const float*)d_in[5];
    const float* wd  = (const float*)d_in[6];
    const float* bnd = (const float*)d_in[7];
    const float* wh1 = (const float*)d_in[8];
    const float* bnh = (const float*)d_in[9];
    const float* wh2 = (const float*)d_in[10];
    const float* bh2 = (const float*)d_in[11];
    float* out = (float*)d_out;

    float *kfeat, *sfeat, *feat, *f2, *h, *wt3k, *wt3s, *wtd, *wth1;
    cudaGetSymbolAddress((void**)&kfeat, g_kfeat);
    cudaGetSymbolAddress((void**)&sfeat, g_sfeat);
    cudaGetSymbolAddress((void**)&feat,  g_feat);
    cudaGetSymbolAddress((void**)&f2,    g_f2);
    cudaGetSymbolAddress((void**)&h,     g_h);
    cudaGetSymbolAddress((void**)&wt3k,  g_wt3k);
    cudaGetSymbolAddress((void**)&wt3s,  g_wt3s);
    cudaGetSymbolAddress((void**)&wtd,   g_wtd);
    cudaGetSymbolAddress((void**)&wth1,  g_wth1);

    // Weight transposes
    transpose_w3_kernel<<<2304, 256>>>(wk, wt3k);
    transpose_w3_kernel<<<2304, 256>>>(ws, wt3s);
    transpose_w1_kernel<768><<<768, 256>>>(wd, wtd);
    transpose_w1_kernel<256><<<256, 256>>>(wh1, wth1);

    // 1) kernel branch: (64,256,7,7) -> (64,256,5,5); N = 1600 px -> 25 tiles
    gemm_conv3x3_kernel<7, 7><<<dim3(25, 4), 128>>>(kernel_in, wt3k, bnk, kfeat);
    // 2) search branch: (64,256,31,31) -> (64,256,29,29); N = 53824 -> 841 tiles
    gemm_conv3x3_kernel<31, 31><<<dim3(841, 4), 128>>>(search_in, wt3s, bns, sfeat);
    // 3) multi-scale depthwise xcorr -> (64,768,25,25)
    multixcorr_kernel<<<dim3(HID_, B_), 256>>>(sfeat, kfeat, feat);
    // 4) 1x1 wd + bn: 768 -> 256 ; N = 40000 -> 625 tiles
    gemm_1x1_kernel<768, false><<<dim3(625, 4), 128>>>(feat, wtd, bnd, f2);
    // 5) 1x1 wh1 + bn + relu: 256 -> 256
    gemm_1x1_kernel<256, true><<<dim3(625, 4), 128>>>(f2, wth1, bnh, h);
    // 6) 1x1 wh2 + bias: 256 -> 10
    conv1x1_out_kernel<<<dim3(B_, 5), 128>>>(h, wh2, bh2, out);
}

// round 4
// speedup vs baseline: 5.4235x; 1.6975x over previous
#include <cuda_runtime.h>
#include <cuda_bf16.h>
#include <math.h>
#include <stdint.h>

#define B_    64
#define CIN_  256
#define HID_  256
#define COUT_ 10
#define EPS_  1e-5f

// Intermediates (device globals; no allocation allowed)
__device__ float g_kfeat[B_ * HID_ * 25];        // (64,256,5,5)
__device__ float g_sfeat[B_ * HID_ * 841];       // (64,256,29,29)
__device__ float g_feat [B_ * HID_ * 3 * 625];   // (64,768,25,25)
__device__ float g_f2   [B_ * HID_ * 625];       // (64,256,25,25)
__device__ float g_h    [B_ * HID_ * 625];       // (64,256,25,25)

// ---------------------------------------------------------------------------
// mma.sync m16n8k16 bf16 (baseline PTX, sm_80+; runs on Blackwell tensor pipe)
// ---------------------------------------------------------------------------
__device__ __forceinline__ void mma_bf16(float* c, const uint32_t* a,
                                         const uint32_t* b) {
    asm volatile(
        "mma.sync.aligned.m16n8k16.row.col.f32.bf16.bf16.f32 "
        "{%0,%1,%2,%3}, {%4,%5,%6,%7}, {%8,%9}, {%0,%1,%2,%3};"
        : "+f"(c[0]), "+f"(c[1]), "+f"(c[2]), "+f"(c[3])
        : "r"(a[0]), "r"(a[1]), "r"(a[2]), "r"(a[3]), "r"(b[0]), "r"(b[1]));
}

__device__ __forceinline__ uint32_t pack2(float a, float b) {
    __nv_bfloat162 h = __floats2bfloat162_rn(a, b);   // .x = a (lo), .y = b (hi)
    return *reinterpret_cast<uint32_t*>(&h);
}
__device__ __forceinline__ float bfval(float a) {
    return __bfloat162float(__float2bfloat16_rn(a));
}

// ---------------------------------------------------------------------------
// Tensor-core GEMM:  C[oc][n] = sum_k W[oc][k] * X[k][n]  + BN (+ReLU)
// MODE 0: implicit-GEMM 3x3 conv (k = ic*9 + tap, matches w natural layout)
// MODE 1: 1x1 conv (k = channel)
// Tile: M=128 x N=128 x K=32/stage.  8 warps as 4(M) x 2(N); warp = 32x64.
// bf16x3 split: acc += aH*bH + aH*bL + aL*bH   (error ~2^-18, fp32-grade)
// smem: A_hi/A_lo/B_hi/B_lo as [row][18 u32] (k-pairs, padded).
// ---------------------------------------------------------------------------
template <int MODE, int HIN, int WIN, int KT, bool RELU>
__global__ void __launch_bounds__(256, 2)
gemm_mma_kernel(const float* __restrict__ in, const float* __restrict__ w,
                const float* __restrict__ bn, float* __restrict__ out) {
    constexpr int WOUT = WIN - 2;
    constexpr int PXB  = (MODE == 0) ? (HIN - 2) * WOUT : 625;
    constexpr int NP   = 64 * PXB;
    constexpr int HW   = HIN * WIN;
    constexpr int S    = KT / 32;
    constexpr int RSTR = 18;                 // u32 words per smem row (16 + 2 pad)
    constexpr int TSZ  = 128 * RSTR;         // one tile in u32

    extern __shared__ uint32_t smem[];
    uint32_t* smA1 = smem;
    uint32_t* smA2 = smem + TSZ;
    uint32_t* smB1 = smem + 2 * TSZ;
    uint32_t* smB2 = smem + 3 * TSZ;

    const int tid  = threadIdx.x;
    const int warp = tid >> 5;
    const int lane = tid & 31;
    const int gid  = lane >> 2;              // 0..7
    const int tig  = lane & 3;               // 0..3
    const int wm   = warp >> 1;              // 0..3  (M group)
    const int wn   = warp & 1;               // 0..1  (N group)
    const int moff = wm * 32;
    const int noff = wn * 64;

    const int oc0 = blockIdx.y * 128;
    const int p0  = blockIdx.x * 128;

    // ---- B gather bases: fixed pixel column per (lane, j) ----
    int  baseN[4];
    bool validN[4];
#pragma unroll
    for (int j = 0; j < 4; j++) {
        int n = p0 + lane + 32 * j;
        validN[j] = (n < NP);
        int nn = validN[j] ? n : 0;
        if (MODE == 0) {
            int b = nn / PXB; int rem = nn - b * PXB;
            int y = rem / WOUT; int x = rem - y * WOUT;
            baseN[j] = (b * CIN_) * HW + y * WIN + x;
        } else {
            int b = nn / 625; int pp = nn - b * 625;
            baseN[j] = b * KT * 625 + pp;
        }
    }

    // ---- accumulators: [mf][nf][4] ----
    float acc[2][8][4];
#pragma unroll
    for (int a = 0; a < 2; a++)
#pragma unroll
        for (int b = 0; b < 8; b++)
#pragma unroll
            for (int c = 0; c < 4; c++) acc[a][b][c] = 0.f;

    const int a_oc    = tid >> 1;            // 0..127 (local oc row)
    const int a_khalf = (tid & 1) * 16;      // 0 or 16 (floats)

    for (int s = 0; s < S; s++) {
        const int k0 = s * 32;
        __syncthreads();

        // ---- stage A: 128 oc x 32 k, split hi/lo ----
        {
            const float* wp = w + (size_t)(oc0 + a_oc) * KT + k0 + a_khalf;
#pragma unroll
            for (int i = 0; i < 4; i++) {
                float4 v = *(const float4*)(wp + 4 * i);
                float hx = bfval(v.x), hy = bfval(v.y);
                float hz = bfval(v.z), hw = bfval(v.w);
                int col = (a_khalf >> 1) + 2 * i;         // word col
                smA1[a_oc * RSTR + col]     = pack2(v.x, v.y);
                smA1[a_oc * RSTR + col + 1] = pack2(v.z, v.w);
                smA2[a_oc * RSTR + col]     = pack2(v.x - hx, v.y - hy);
                smA2[a_oc * RSTR + col + 1] = pack2(v.z - hz, v.w - hw);
            }
        }
        // ---- stage B: 128 n x 32 k (warp supplies k rows warp*4..+3) ----
        {
            int offk[4];
#pragma unroll
            for (int kk = 0; kk < 4; kk++) {
                int k = k0 + warp * 4 + kk;
                if (MODE == 0) {
                    int ic = k / 9; int tap = k - ic * 9;
                    int ky = tap / 3; int kx = tap - ky * 3;
                    offk[kk] = ic * HW + ky * WIN + kx;
                } else {
                    offk[kk] = k * 625;
                }
            }
#pragma unroll
            for (int j = 0; j < 4; j++) {
                float v0 = validN[j] ? __ldg(in + baseN[j] + offk[0]) : 0.f;
                float v1 = validN[j] ? __ldg(in + baseN[j] + offk[1]) : 0.f;
                float v2 = validN[j] ? __ldg(in + baseN[j] + offk[2]) : 0.f;
                float v3 = validN[j] ? __ldg(in + baseN[j] + offk[3]) : 0.f;
                float h0 = bfval(v0), h1 = bfval(v1), h2 = bfval(v2), h3 = bfval(v3);
                int n = lane + 32 * j;
                int col = warp * 2;
                smB1[n * RSTR + col]     = pack2(v0, v1);
                smB1[n * RSTR + col + 1] = pack2(v2, v3);
                smB2[n * RSTR + col]     = pack2(v0 - h0, v1 - h1);
                smB2[n * RSTR + col + 1] = pack2(v2 - h2, v3 - h3);
            }
        }
        __syncthreads();

        // ---- 2 chunks of k16 ----
#pragma unroll
        for (int kc = 0; kc < 2; kc++) {
            const int w0 = kc * 8 + tig;
            const int w1 = w0 + 4;
            uint32_t aH[2][4], aL[2][4];
#pragma unroll
            for (int mf = 0; mf < 2; mf++) {
                int r0 = (moff + mf * 16 + gid) * RSTR;
                int r1 = r0 + 8 * RSTR;
                aH[mf][0] = smA1[r0 + w0]; aH[mf][1] = smA1[r1 + w0];
                aH[mf][2] = smA1[r0 + w1]; aH[mf][3] = smA1[r1 + w1];
                aL[mf][0] = smA2[r0 + w0]; aL[mf][1] = smA2[r1 + w0];
                aL[mf][2] = smA2[r0 + w1]; aL[mf][3] = smA2[r1 + w1];
            }
#pragma unroll
            for (int nf = 0; nf < 8; nf++) {
                int nr = (noff + nf * 8 + gid) * RSTR;
                uint32_t bH[2] = {smB1[nr + w0], smB1[nr + w1]};
                uint32_t bL[2] = {smB2[nr + w0], smB2[nr + w1]};
#pragma unroll
                for (int mf = 0; mf < 2; mf++) {
                    mma_bf16(acc[mf][nf], aH[mf], bH);
                    mma_bf16(acc[mf][nf], aH[mf], bL);
                    mma_bf16(acc[mf][nf], aL[mf], bH);
                }
            }
        }
    }

    // ---- epilogue: frags -> padded smem -> BN(+ReLU) -> coalesced NCHW ----
    __syncthreads();
    float* Cs = (float*)smem;                // 128 x 132 fp32 (staging dead)
#pragma unroll
    for (int mf = 0; mf < 2; mf++) {
#pragma unroll
        for (int nf = 0; nf < 8; nf++) {
            int m0 = moff + mf * 16 + gid;
            int nl = noff + nf * 8 + 2 * tig;
            *(float2*)&Cs[m0 * 132 + nl]       = make_float2(acc[mf][nf][0], acc[mf][nf][1]);
            *(float2*)&Cs[(m0 + 8) * 132 + nl] = make_float2(acc[mf][nf][2], acc[mf][nf][3]);
        }
    }
    __syncthreads();

    for (int t = warp; t < 128; t += 8) {
        const int oc = oc0 + t;
        const float g  = bn[oc];
        const float be = bn[256 + oc];
        const float mm = bn[512 + oc];
        const float vv = bn[768 + oc];
        const float inv  = g * rsqrtf(vv + EPS_);
        const float bias = be - mm * inv;
#pragma unroll
        for (int cc0 = 0; cc0 < 128; cc0 += 32) {
            int cc = cc0 + lane;
            int n = p0 + cc;
            if (n < NP) {
                int b = n / PXB; int rq = n - b * PXB;
                float val = Cs[t * 132 + cc] * inv + bias;
                if (RELU) val = fmaxf(val, 0.f);
                out[((size_t)(b * 256 + oc)) * PXB + rq] = val;
            }
        }
    }
}

// ---------------------------------------------------------------------------
// Multi-scale depthwise xcorr (all 3 nested scales in one 5x5 pass).
// ---------------------------------------------------------------------------
__global__ void multixcorr_kernel(const float* __restrict__ s,
                                  const float* __restrict__ k,
                                  float* __restrict__ feat) {
    const int c = blockIdx.x;
    const int b = blockIdx.y;

    __shared__ float ss[29 * 29];
    __shared__ float kk[25];

    const float* sp = s + ((size_t)b * HID_ + c) * 841;
    const float* kp = k + ((size_t)b * HID_ + c) * 25;

    for (int i = threadIdx.x; i < 841; i += blockDim.x) ss[i] = sp[i];
    if (threadIdx.x < 25) kk[threadIdx.x] = kp[threadIdx.x];
    __syncthreads();

    float* f0 = feat + ((size_t)b * (3 * HID_) + c) * 625;
    float* f1 = f0 + (size_t)HID_ * 625;
    float* f2 = f1 + (size_t)HID_ * 625;

    for (int p = threadIdx.x; p < 625; p += blockDim.x) {
        const int y = p / 25, x = p - (p / 25) * 25;
        float s_full = 0.f, s_in = 0.f;
#pragma unroll
        for (int dy = 0; dy < 5; dy++)
#pragma unroll
            for (int dx = 0; dx < 5; dx++) {
                float vv = ss[(y + dy) * 29 + (x + dx)] * kk[dy * 5 + dx];
                s_full += vv;
                if (dy >= 1 && dy <= 3 && dx >= 1 && dx <= 3) s_in += vv;
            }
        f0[p] = s_full;
        f1[p] = s_in;
        f2[p] = ss[(y + 2) * 29 + (x + 2)] * kk[12];
    }
}

// ---------------------------------------------------------------------------
// Final 1x1: (B,256,625) x (10,256) + bias -> (B,10,625). grid (B, 5).
// ---------------------------------------------------------------------------
__global__ void conv1x1_out_kernel(const float* __restrict__ in,
                                   const float* __restrict__ w,
                                   const float* __restrict__ bias,
                                   float* __restrict__ out) {
    const int b = blockIdx.x;
    const int chunk = blockIdx.y;

    __shared__ float wsm[COUT_ * HID_];
    for (int i = threadIdx.x; i < COUT_ * HID_; i += blockDim.x) wsm[i] = w[i];
    __syncthreads();

    const float* ib = in + (size_t)b * HID_ * 625;
    float* ob = out + (size_t)b * COUT_ * 625;

    const int pend = min(625, (chunk + 1) * 125);
    for (int p = chunk * 125 + threadIdx.x; p < pend; p += blockDim.x) {
        float acc[COUT_];
#pragma unroll
        for (int o = 0; o < COUT_; o++) acc[o] = bias[o];
        for (int c = 0; c < HID_; c++) {
            float vv = ib[(size_t)c * 625 + p];
#pragma unroll
            for (int o = 0; o < COUT_; o++) acc[o] = fmaf(vv, wsm[o * HID_ + c], acc[o]);
        }
#pragma unroll
        for (int o = 0; o < COUT_; o++) ob[(size_t)o * 625 + p] = acc[o];
    }
}

// ---------------------------------------------------------------------------
extern "C" void kernel_launch(void* const* d_in, const int* in_sizes, int n_in,
                              void* d_out, int out_size) {
    const float* kernel_in = (const float*)d_in[0];
    const float* search_in = (const float*)d_in[1];
    const float* wk  = (const float*)d_in[2];
    const float* bnk = (const float*)d_in[3];
    const float* ws  = (const float*)d_in[4];
    const float* bns = (const float*)d_in[5];
    const float* wd  = (const float*)d_in[6];
    const float* bnd = (const float*)d_in[7];
    const float* wh1 = (const float*)d_in[8];
    const float* bnh = (const float*)d_in[9];
    const float* wh2 = (const float*)d_in[10];
    const float* bh2 = (const float*)d_in[11];
    float* out = (float*)d_out;

    float *kfeat, *sfeat, *feat, *f2, *h;
    cudaGetSymbolAddress((void**)&kfeat, g_kfeat);
    cudaGetSymbolAddress((void**)&sfeat, g_sfeat);
    cudaGetSymbolAddress((void**)&feat,  g_feat);
    cudaGetSymbolAddress((void**)&f2,    g_f2);
    cudaGetSymbolAddress((void**)&h,     g_h);

    constexpr int SMEM = 128 * 132 * 4;    // 67584 (>= 4 staging tiles of 9216)

    cudaFuncSetAttribute(gemm_mma_kernel<0, 7, 7, 2304, true>,
                         cudaFuncAttributeMaxDynamicSharedMemorySize, SMEM);
    cudaFuncSetAttribute(gemm_mma_kernel<0, 31, 31, 2304, true>,
                         cudaFuncAttributeMaxDynamicSharedMemorySize, SMEM);
    cudaFuncSetAttribute(gemm_mma_kernel<1, 27, 27, 768, false>,
                         cudaFuncAttributeMaxDynamicSharedMemorySize, SMEM);
    cudaFuncSetAttribute(gemm_mma_kernel<1, 27, 27, 256, true>,
                         cudaFuncAttributeMaxDynamicSharedMemorySize, SMEM);

    // 1) kernel branch: NP=1600 -> 13 N-tiles, 2 M-tiles
    gemm_mma_kernel<0, 7, 7, 2304, true><<<dim3(13, 2), 256, SMEM>>>(kernel_in, wk, bnk, kfeat);
    // 2) search branch: NP=53824 -> 421 N-tiles
    gemm_mma_kernel<0, 31, 31, 2304, true><<<dim3(421, 2), 256, SMEM>>>(search_in, ws, bns, sfeat);
    // 3) multi-scale depthwise xcorr -> (64,768,25,25)
    multixcorr_kernel<<<dim3(HID_, B_), 256>>>(sfeat, kfeat, feat);
    // 4) 1x1 wd + bn: 768 -> 256 ; NP=40000 -> 313 N-tiles
    gemm_mma_kernel<1, 27, 27, 768, false><<<dim3(313, 2), 256, SMEM>>>(feat, wd, bnd, f2);
    // 5) 1x1 wh1 + bn + relu: 256 -> 256
    gemm_mma_kernel<1, 27, 27, 256, true><<<dim3(313, 2), 256, SMEM>>>(f2, wh1, bnh, h);
    // 6) 1x1 wh2 + bias: 256 -> 10
    conv1x1_out_kernel<<<dim3(B_, 5), 128>>>(h, wh2, bh2, out);
}

// round 5
// speedup vs baseline: 6.8715x; 1.2670x over previous
#include <cuda_runtime.h>
#include <cuda_bf16.h>
#include <math.h>
#include <stdint.h>

#define B_    64
#define CIN_  256
#define HID_  256
#define COUT_ 10
#define EPS_  1e-5f

// ---------------------------------------------------------------------------
// Device globals (no runtime allocation allowed)
// ---------------------------------------------------------------------------
// fp32 intermediates
__device__ float g_kfeat[B_ * HID_ * 25];        // (64,256,5,5)
__device__ float g_sfeat[B_ * HID_ * 841];       // (64,256,29,29)
__device__ float g_h    [B_ * HID_ * 625];       // (64,256,25,25)
// packed bf16 hi/lo weights, smem-ready order
__device__ __align__(16) uint32_t g_wk_hi[9 * 256 * 128], g_wk_lo[9 * 256 * 128];
__device__ __align__(16) uint32_t g_ws_hi[9 * 256 * 128], g_ws_lo[9 * 256 * 128];
__device__ __align__(16) uint32_t g_wd_hi[256 * 384],     g_wd_lo[256 * 384];
__device__ __align__(16) uint32_t g_wh1_hi[256 * 128],    g_wh1_lo[256 * 128];
// packed bf16 hi/lo inputs: [icpair 128][b 64][HW]
__device__ __align__(16) uint32_t g_kin_hi[128 * 64 * 49],  g_kin_lo[128 * 64 * 49];
__device__ __align__(16) uint32_t g_sin_hi[128 * 64 * 961], g_sin_lo[128 * 64 * 961];
// packed bf16 hi/lo activations: [kpair][n=40000]
__device__ __align__(16) uint32_t g_featP_hi[384 * 40000], g_featP_lo[384 * 40000];
__device__ __align__(16) uint32_t g_f2P_hi [128 * 40000], g_f2P_lo [128 * 40000];

// ---------------------------------------------------------------------------
// PTX helpers (baseline ISA only; compiles for plain compute_103)
// ---------------------------------------------------------------------------
__device__ __forceinline__ void mma_bf16(float* c, const uint32_t* a,
                                         const uint32_t* b) {
    asm volatile(
        "mma.sync.aligned.m16n8k16.row.col.f32.bf16.bf16.f32 "
        "{%0,%1,%2,%3}, {%4,%5,%6,%7}, {%8,%9}, {%0,%1,%2,%3};"
        : "+f"(c[0]), "+f"(c[1]), "+f"(c[2]), "+f"(c[3])
        : "r"(a[0]), "r"(a[1]), "r"(a[2]), "r"(a[3]), "r"(b[0]), "r"(b[1]));
}

__device__ __forceinline__ void ldm4(uint32_t* d, uint32_t addr) {
    asm volatile("ldmatrix.sync.aligned.m8n8.x4.shared.b16 {%0,%1,%2,%3}, [%4];"
                 : "=r"(d[0]), "=r"(d[1]), "=r"(d[2]), "=r"(d[3]) : "r"(addr));
}

__device__ __forceinline__ uint32_t smem_u32(const void* p) {
    uint32_t a;
    asm("{ .reg .u64 t; cvta.to.shared.u64 t, %1; cvt.u32.u64 %0, t; }"
        : "=r"(a) : "l"(p));
    return a;
}

#define CP_ASYNC16(dst, src) \
    asm volatile("cp.async.cg.shared.global [%0], [%1], 16;" :: "r"(dst), "l"(src))
#define CP_COMMIT()  asm volatile("cp.async.commit_group;")
#define CP_WAIT0()   asm volatile("cp.async.wait_group 0;" ::: "memory")

// split (a,b) into bf16 hi pair + bf16 residual pair
__device__ __forceinline__ void split2(float a, float b, uint32_t& hi, uint32_t& lo) {
    __nv_bfloat162 h = __floats2bfloat162_rn(a, b);
    hi = *reinterpret_cast<uint32_t*>(&h);
    float ra = a - __bfloat162float(h.x);
    float rb = b - __bfloat162float(h.y);
    __nv_bfloat162 l = __floats2bfloat162_rn(ra, rb);
    lo = *reinterpret_cast<uint32_t*>(&l);
}

__device__ __forceinline__ void split1_u16(float v, uint16_t& hi, uint16_t& lo) {
    __nv_bfloat16 h = __float2bfloat16_rn(v);
    hi = *reinterpret_cast<uint16_t*>(&h);
    float r = v - __bfloat162float(h);
    __nv_bfloat16 l = __float2bfloat16_rn(r);
    lo = *reinterpret_cast<uint16_t*>(&l);
}

// ---------------------------------------------------------------------------
// Prep kernels (tiny; run each launch)
// ---------------------------------------------------------------------------
// w(oc,ic,3,3) -> wP[tap][oc][icpair] hi/lo
__global__ void prep_w3(const float* __restrict__ w,
                        uint32_t* __restrict__ oh, uint32_t* __restrict__ ol) {
    int idx = blockIdx.x * 256 + threadIdx.x;
    if (idx >= 9 * 256 * 128) return;
    int tap = idx >> 15;
    int rem = idx & 32767;
    int oc = rem >> 7, p = rem & 127;
    float a = w[(size_t)oc * 2304 + (2 * p) * 9 + tap];
    float b = w[(size_t)oc * 2304 + (2 * p + 1) * 9 + tap];
    split2(a, b, oh[idx], ol[idx]);
}

// w(oc,K) -> wP[oc][kpair] hi/lo
template <int K>
__global__ void prep_w1(const float* __restrict__ w,
                        uint32_t* __restrict__ oh, uint32_t* __restrict__ ol) {
    int idx = blockIdx.x * 256 + threadIdx.x;
    if (idx >= 256 * (K / 2)) return;
    int oc = idx / (K / 2), kp = idx - oc * (K / 2);
    split2(w[(size_t)oc * K + 2 * kp], w[(size_t)oc * K + 2 * kp + 1],
           oh[idx], ol[idx]);
}

// in(b,256,HW) -> inP[icpair][b][HW] hi/lo
template <int HW>
__global__ void prep_in(const float* __restrict__ in,
                        uint32_t* __restrict__ oh, uint32_t* __restrict__ ol) {
    int idx = blockIdx.x * 256 + threadIdx.x;
    if (idx >= 128 * 64 * HW) return;
    int p = idx / (64 * HW);
    int rem = idx - p * (64 * HW);
    int b = rem / HW, pix = rem - b * HW;
    const float* src = in + (size_t)b * 256 * HW + (2 * p) * HW + pix;
    split2(src[0], src[HW], oh[idx], ol[idx]);
}

// ---------------------------------------------------------------------------
// Tensor-core GEMM: C[oc][n] = sum_k A[oc][k] * B[k][n], + BN (+ReLU)
// MODE 0: implicit-GEMM 3x3 conv, k = tap*256 + ic  (A/B pre-packed for this)
// MODE 1: 1x1 conv, k = channel, B = packed [kpair][40000]
// EPI 0: fp32 NCHW store.  EPI 1: packed bf16 hi/lo [kpair][n] store.
// Tile M=128 x N=128 x K=32/stage; 8 warps 4(M)x2(N); bf16x3 split (3 mma).
// Double-buffered staging: cp.async A + register-prefetched B.
// ---------------------------------------------------------------------------
template <int MODE, int HIN, int WIN, int KT, bool RELU, int EPI>
__global__ void __launch_bounds__(256, 2)
gemm_mma2_kernel(const uint32_t* __restrict__ bH_src, const uint32_t* __restrict__ bL_src,
                 const uint32_t* __restrict__ aH_src, const uint32_t* __restrict__ aL_src,
                 const float* __restrict__ bn, float* __restrict__ out,
                 uint16_t* __restrict__ outH, uint16_t* __restrict__ outL) {
    constexpr int WOUT = WIN - 2;
    constexpr int PXB  = (MODE == 0) ? (HIN - 2) * WOUT : 625;
    constexpr int NP   = 64 * PXB;
    constexpr int HW   = HIN * WIN;
    constexpr int S    = KT / 32;
    constexpr int RSTR = 20;
    constexpr int TILE = 128 * RSTR;
    constexpr int AR   = (MODE == 0) ? 128 : (KT / 2);
    constexpr int PLSTR = 64 * HW;

    extern __shared__ uint32_t smem[];
    const uint32_t smb = smem_u32(smem);

    const int tid  = threadIdx.x;
    const int warp = tid >> 5;
    const int lane = tid & 31;
    const int gid  = lane >> 2;
    const int tig  = lane & 3;
    const int moff = (warp >> 1) * 32;
    const int noff = (warp & 1) * 64;

    const int oc0 = blockIdx.y * 128;
    const int p0  = blockIdx.x * 128;

    // ldmatrix lane address components
    const int aRow = lane & 15;
    const int aCol = (lane >> 4) * 4;
    const int bRow = (lane & 7) + ((lane >> 4) & 1) * 8;
    const int bCol = ((lane >> 3) & 1) * 4;

    // B gather: thread owns pixel n = tid & 127 (across all tasks)
    const int nloc  = tid & 127;
    const int nglob = p0 + nloc;
    const bool nvalid = (nglob < NP);
    int bbase = 0;
    if (MODE == 0) {
        int nn = nvalid ? nglob : 0;
        int b = nn / PXB; int rem = nn - b * PXB;
        int y = rem / WOUT; int x = rem - y * WOUT;
        bbase = b * HW + y * WIN + x;
    }

    float acc[2][8][4];
#pragma unroll
    for (int a = 0; a < 2; a++)
#pragma unroll
        for (int b = 0; b < 8; b++)
#pragma unroll
            for (int c = 0; c < 4; c++) acc[a][b][c] = 0.f;

    // ---- staging helpers ----
    auto prefetchB = [&](int s, uint32_t v[4][4]) {
        int tap = 0, tapoff = 0, plane0 = 0;
        if (MODE == 0) {
            tap = s >> 3; plane0 = (s & 7) * 16;
            tapoff = (tap / 3) * WIN + (tap % 3);
        }
#pragma unroll
        for (int i = 0; i < 4; i++) {
            int task = tid + 256 * i;
            int hl = task >> 9;
            int wg = (task >> 7) & 3;
            const uint32_t* src = hl ? bL_src : bH_src;
#pragma unroll
            for (int j = 0; j < 4; j++) {
                int w = wg * 4 + j;
                long addr = (MODE == 0)
                    ? (long)(plane0 + w) * PLSTR + bbase + tapoff
                    : (long)(s * 16 + w) * 40000 + nglob;
                v[i][j] = nvalid ? __ldg(src + addr) : 0u;
            }
        }
    };
    auto storeB = [&](int buf, uint32_t v[4][4]) {
#pragma unroll
        for (int i = 0; i < 4; i++) {
            int task = tid + 256 * i;
            int hl = task >> 9;
            int wg = (task >> 7) & 3;
            uint32_t* dst = &smem[(buf * 4 + 2 + hl) * TILE + nloc * RSTR + wg * 4];
            *reinterpret_cast<uint4*>(dst) =
                make_uint4(v[i][0], v[i][1], v[i][2], v[i][3]);
        }
    };
    auto stageA = [&](int buf, int s) {
        int abase;
        if (MODE == 0) {
            int tap = s >> 3; int plane0 = (s & 7) * 16;
            abase = tap * 32768 + oc0 * 128 + plane0;
        } else {
            abase = oc0 * (KT / 2) + s * 16;
        }
#pragma unroll
        for (int i = 0; i < 4; i++) {
            int task = tid + 256 * i;
            int hl = task >> 9;
            int rem = task & 511;
            int r = rem >> 2;
            int c = (rem & 3) * 4;
            const uint32_t* src = (hl ? aL_src : aH_src) + abase + r * AR + c;
            uint32_t dst = smb + ((buf * 4 + hl) * TILE + r * RSTR + c) * 4;
            CP_ASYNC16(dst, src);
        }
    };

    // ---- prologue: stage s=0 into buf 0 ----
    {
        uint32_t v[4][4];
        prefetchB(0, v);
        storeB(0, v);
        stageA(0, 0);
        CP_COMMIT();
    }

    // ---- main pipeline ----
    for (int s = 0; s < S; s++) {
        const int buf = s & 1;
        CP_WAIT0();
        __syncthreads();

        uint32_t vpre[4][4];
        const bool have = (s + 1 < S);
        if (have) prefetchB(s + 1, vpre);

        // consume buffer buf
        const uint32_t smA_hi = smb + (buf * 4 + 0) * TILE * 4;
        const uint32_t smA_lo = smb + (buf * 4 + 1) * TILE * 4;
        const uint32_t smB_hi = smb + (buf * 4 + 2) * TILE * 4;
        const uint32_t smB_lo = smb + (buf * 4 + 3) * TILE * 4;
#pragma unroll
        for (int kc = 0; kc < 2; kc++) {
            uint32_t aH[2][4], aL[2][4];
#pragma unroll
            for (int mf = 0; mf < 2; mf++) {
                uint32_t off = ((moff + mf * 16 + aRow) * RSTR + kc * 8 + aCol) * 4;
                ldm4(aH[mf], smA_hi + off);
                ldm4(aL[mf], smA_lo + off);
            }
#pragma unroll
            for (int nfp = 0; nfp < 4; nfp++) {
                uint32_t boff = ((noff + nfp * 16 + bRow) * RSTR + kc * 8 + bCol) * 4;
                uint32_t bHf[4], bLf[4];
                ldm4(bHf, smB_hi + boff);
                ldm4(bLf, smB_lo + boff);
#pragma unroll
                for (int snf = 0; snf < 2; snf++) {
                    int nf = nfp * 2 + snf;
#pragma unroll
                    for (int mf = 0; mf < 2; mf++) {
                        mma_bf16(acc[mf][nf], aH[mf], &bHf[2 * snf]);
                        mma_bf16(acc[mf][nf], aH[mf], &bLf[2 * snf]);
                        mma_bf16(acc[mf][nf], aL[mf], &bHf[2 * snf]);
                    }
                }
            }
        }

        if (have) {
            storeB(buf ^ 1, vpre);
            stageA(buf ^ 1, s + 1);
            CP_COMMIT();
        }
    }

    // ---- epilogue: frags -> padded smem -> BN(+ReLU) -> store ----
    __syncthreads();
    float* Cs = (float*)smem;                // 128 x 132 fp32
#pragma unroll
    for (int mf = 0; mf < 2; mf++) {
#pragma unroll
        for (int nf = 0; nf < 8; nf++) {
            int m0 = moff + mf * 16 + gid;
            int nl = noff + nf * 8 + 2 * tig;
            *(float2*)&Cs[m0 * 132 + nl]       = make_float2(acc[mf][nf][0], acc[mf][nf][1]);
            *(float2*)&Cs[(m0 + 8) * 132 + nl] = make_float2(acc[mf][nf][2], acc[mf][nf][3]);
        }
    }
    __syncthreads();

    for (int t = warp; t < 128; t += 8) {
        const int oc = oc0 + t;
        const float g  = bn[oc];
        const float be = bn[256 + oc];
        const float mm = bn[512 + oc];
        const float vv = bn[768 + oc];
        const float inv  = g * rsqrtf(vv + EPS_);
        const float bias = be - mm * inv;
#pragma unroll
        for (int cc0 = 0; cc0 < 128; cc0 += 32) {
            int cc = cc0 + lane;
            int n = p0 + cc;
            if (n < NP) {
                float val = Cs[t * 132 + cc] * inv + bias;
                if (RELU) val = fmaxf(val, 0.f);
                if (EPI == 0) {
                    int b = n / PXB; int rq = n - b * PXB;
                    out[((size_t)(b * 256 + oc)) * PXB + rq] = val;
                } else {
                    uint16_t h, l;
                    split1_u16(val, h, l);
                    size_t off = (size_t)(oc >> 1) * 80000 + n * 2 + (oc & 1);
                    outH[off] = h;
                    outL[off] = l;
                }
            }
        }
    }
}

// ---------------------------------------------------------------------------
// Multi-scale depthwise xcorr; emits packed bf16 hi/lo [kpair][n] directly.
// ---------------------------------------------------------------------------
__global__ void multixcorr_kernel(const float* __restrict__ s,
                                  const float* __restrict__ k,
                                  uint32_t* __restrict__ fh,
                                  uint32_t* __restrict__ fl) {
    const int c = blockIdx.x;
    const int b = blockIdx.y;

    __shared__ float ss[29 * 29];
    __shared__ float kk[25];

    const float* sp = s + ((size_t)b * HID_ + c) * 841;
    const float* kp = k + ((size_t)b * HID_ + c) * 25;

    for (int i = threadIdx.x; i < 841; i += blockDim.x) ss[i] = sp[i];
    if (threadIdx.x < 25) kk[threadIdx.x] = kp[threadIdx.x];
    __syncthreads();

    uint16_t* fH = (uint16_t*)fh;
    uint16_t* fL = (uint16_t*)fl;
    const int half = c & 1;
    const int kp0 = c >> 1;

    for (int p = threadIdx.x; p < 625; p += blockDim.x) {
        const int y = p / 25, x = p - (p / 25) * 25;
        float s_full = 0.f, s_in = 0.f;
#pragma unroll
        for (int dy = 0; dy < 5; dy++)
#pragma unroll
            for (int dx = 0; dx < 5; dx++) {
                float vv = ss[(y + dy) * 29 + (x + dx)] * kk[dy * 5 + dx];
                s_full += vv;
                if (dy >= 1 && dy <= 3 && dx >= 1 && dx <= 3) s_in += vv;
            }
        float s_c = ss[(y + 2) * 29 + (x + 2)] * kk[12];
        const int n = b * 625 + p;
        uint16_t h, l;
        split1_u16(s_full, h, l);
        fH[(size_t)kp0 * 80000 + n * 2 + half] = h;
        fL[(size_t)kp0 * 80000 + n * 2 + half] = l;
        split1_u16(s_in, h, l);
        fH[(size_t)(128 + kp0) * 80000 + n * 2 + half] = h;
        fL[(size_t)(128 + kp0) * 80000 + n * 2 + half] = l;
        split1_u16(s_c, h, l);
        fH[(size_t)(256 + kp0) * 80000 + n * 2 + half] = h;
        fL[(size_t)(256 + kp0) * 80000 + n * 2 + half] = l;
    }
}

// ---------------------------------------------------------------------------
// Final 1x1: (B,256,625) x (10,256) + bias -> (B,10,625). grid (B, 5).
// ---------------------------------------------------------------------------
__global__ void conv1x1_out_kernel(const float* __restrict__ in,
                                   const float* __restrict__ w,
                                   const float* __restrict__ bias,
                                   float* __restrict__ out) {
    const int b = blockIdx.x;
    const int chunk = blockIdx.y;

    __shared__ float wsm[COUT_ * HID_];
    for (int i = threadIdx.x; i < COUT_ * HID_; i += blockDim.x) wsm[i] = w[i];
    __syncthreads();

    const float* ib = in + (size_t)b * HID_ * 625;
    float* ob = out + (size_t)b * COUT_ * 625;

    const int pend = min(625, (chunk + 1) * 125);
    for (int p = chunk * 125 + threadIdx.x; p < pend; p += blockDim.x) {
        float acc[COUT_];
#pragma unroll
        for (int o = 0; o < COUT_; o++) acc[o] = bias[o];
        for (int c = 0; c < HID_; c++) {
            float vv = ib[(size_t)c * 625 + p];
#pragma unroll
            for (int o = 0; o < COUT_; o++) acc[o] = fmaf(vv, wsm[o * HID_ + c], acc[o]);
        }
#pragma unroll
        for (int o = 0; o < COUT_; o++) ob[(size_t)o * 625 + p] = acc[o];
    }
}

// ---------------------------------------------------------------------------
extern "C" void kernel_launch(void* const* d_in, const int* in_sizes, int n_in,
                              void* d_out, int out_size) {
    const float* kernel_in = (const float*)d_in[0];
    const float* search_in = (const float*)d_in[1];
    const float* wk  = (const float*)d_in[2];
    const float* bnk = (const float*)d_in[3];
    const float* ws  = (const float*)d_in[4];
    const float* bns = (const float*)d_in[5];
    const float* wd  = (const float*)d_in[6];
    const float* bnd = (const float*)d_in[7];
    const float* wh1 = (const float*)d_in[8];
    const float* bnh = (const float*)d_in[9];
    const float* wh2 = (const float*)d_in[10];
    const float* bh2 = (const float*)d_in[11];
    float* out = (float*)d_out;

    float *kfeat, *sfeat, *h;
    uint32_t *wkh, *wkl, *wsh, *wsl, *wdh, *wdl, *wh1h, *wh1l;
    uint32_t *kinh, *kinl, *sinh, *sinl, *fph, *fpl, *f2h, *f2l;
    cudaGetSymbolAddress((void**)&kfeat, g_kfeat);
    cudaGetSymbolAddress((void**)&sfeat, g_sfeat);
    cudaGetSymbolAddress((void**)&h,     g_h);
    cudaGetSymbolAddress((void**)&wkh, g_wk_hi);  cudaGetSymbolAddress((void**)&wkl, g_wk_lo);
    cudaGetSymbolAddress((void**)&wsh, g_ws_hi);  cudaGetSymbolAddress((void**)&wsl, g_ws_lo);
    cudaGetSymbolAddress((void**)&wdh, g_wd_hi);  cudaGetSymbolAddress((void**)&wdl, g_wd_lo);
    cudaGetSymbolAddress((void**)&wh1h, g_wh1_hi); cudaGetSymbolAddress((void**)&wh1l, g_wh1_lo);
    cudaGetSymbolAddress((void**)&kinh, g_kin_hi); cudaGetSymbolAddress((void**)&kinl, g_kin_lo);
    cudaGetSymbolAddress((void**)&sinh, g_sin_hi); cudaGetSymbolAddress((void**)&sinl, g_sin_lo);
    cudaGetSymbolAddress((void**)&fph, g_featP_hi); cudaGetSymbolAddress((void**)&fpl, g_featP_lo);
    cudaGetSymbolAddress((void**)&f2h, g_f2P_hi);  cudaGetSymbolAddress((void**)&f2l, g_f2P_lo);

    constexpr int SMEM = 8 * 128 * 20 * 4;  // 81920

    cudaFuncSetAttribute(gemm_mma2_kernel<0, 7, 7, 2304, true, 0>,
                         cudaFuncAttributeMaxDynamicSharedMemorySize, SMEM);
    cudaFuncSetAttribute(gemm_mma2_kernel<0, 31, 31, 2304, true, 0>,
                         cudaFuncAttributeMaxDynamicSharedMemorySize, SMEM);
    cudaFuncSetAttribute(gemm_mma2_kernel<1, 3, 3, 768, false, 1>,
                         cudaFuncAttributeMaxDynamicSharedMemorySize, SMEM);
    cudaFuncSetAttribute(gemm_mma2_kernel<1, 3, 3, 256, true, 0>,
                         cudaFuncAttributeMaxDynamicSharedMemorySize, SMEM);

    // -- prep (independent, tiny) --
    prep_w3<<<(9 * 256 * 128 + 255) / 256, 256>>>(wk, wkh, wkl);
    prep_w3<<<(9 * 256 * 128 + 255) / 256, 256>>>(ws, wsh, wsl);
    prep_w1<768><<<(256 * 384 + 255) / 256, 256>>>(wd, wdh, wdl);
    prep_w1<256><<<(256 * 128 + 255) / 256, 256>>>(wh1, wh1h, wh1l);
    prep_in<49><<<(128 * 64 * 49 + 255) / 256, 256>>>(kernel_in, kinh, kinl);
    prep_in<961><<<(128 * 64 * 961 + 255) / 256, 256>>>(search_in, sinh, sinl);

    // 1) kernel branch conv3x3+bn+relu -> g_kfeat ; NP=1600 -> 13 tiles
    gemm_mma2_kernel<0, 7, 7, 2304, true, 0><<<dim3(13, 2), 256, SMEM>>>(
        kinh, kinl, wkh, wkl, bnk, kfeat, nullptr, nullptr);
    // 2) search branch -> g_sfeat ; NP=53824 -> 421 tiles
    gemm_mma2_kernel<0, 31, 31, 2304, true, 0><<<dim3(421, 2), 256, SMEM>>>(
        sinh, sinl, wsh, wsl, bns, sfeat, nullptr, nullptr);
    // 3) xcorr -> packed featP
    multixcorr_kernel<<<dim3(HID_, B_), 256>>>(sfeat, kfeat, fph, fpl);
    // 4) wd + bn (no relu) -> packed f2P ; NP=40000 -> 313 tiles
    gemm_mma2_kernel<1, 3, 3, 768, false, 1><<<dim3(313, 2), 256, SMEM>>>(
        fph, fpl, wdh, wdl, bnd, nullptr, (uint16_t*)f2h, (uint16_t*)f2l);
    // 5) wh1 + bn + relu -> g_h (fp32)
    gemm_mma2_kernel<1, 3, 3, 256, true, 0><<<dim3(313, 2), 256, SMEM>>>(
        f2h, f2l, wh1h, wh1l, bnh, h, nullptr, nullptr);
    // 6) wh2 + bias -> out
    conv1x1_out_kernel<<<dim3(B_, 5), 128>>>(h, wh2, bh2, out);
}